// round 3
// baseline (speedup 1.0000x reference)
#include <cuda_runtime.h>

// x: (4, 32, 512, 512) fp32 ; bias: (1, 32, 1, 1) fp32
// out: [G1 | G2 | G3], each (4, 32, 512, 512) fp32
//
// G1[h,w] = (h>=1 && w>=1) ? exp(-(x[h-1,w-1]-x[h,w])^2) + bias : bias
// G2[h,w] = (w>=1)          ? exp(-(x[h,  w-1]-x[h,w])^2) + bias : bias
// G3[h,w] = (h<H-1 && w>=1) ? exp(-(x[h+1,w-1]-x[h,w])^2) + bias : bias
//
// Each thread handles TWO vertically-adjacent positions (h0=2*hp, h1=h0+1)
// for one float4 column: loads rows h0-1..h1+1 (4 vec loads) and writes
// 6 output float4s (2 positions x 3 gates).

#define H 512
#define W 512
#define WV (W / 4)          // 128 float4 per row
#define HP (H / 2)          // 256 row pairs
#define CHANS 32

__global__ __launch_bounds__(256) void embeded_gate_kernel(
    const float* __restrict__ x,
    const float* __restrict__ bias,
    float* __restrict__ out,
    long long n_elems)       // elements per gate tensor
{
    const int idx = blockIdx.x * blockDim.x + threadIdx.x;
    // idx -> (bc, hp, v)
    const int v  = idx & (WV - 1);
    const int hp = (idx >> 7) & (HP - 1);
    const int bc = idx >> 15;
    const int c  = bc & (CHANS - 1);

    const int h0 = hp << 1;
    const int h1 = h0 + 1;

    const float bi = __ldg(&bias[c]);

    const float4* __restrict__ x4 = reinterpret_cast<const float4*>(x);
    const long long base4 = (long long)bc * (H * WV);
    const long long baseS = (long long)bc * (H * W);
    const int w0 = v << 2;
    const bool vs = (v > 0);

    // ---- load 4 rows: A=h0-1, B=h0, C=h1, D=h1+1 ----
    float4 A4 = make_float4(0.f, 0.f, 0.f, 0.f);
    float lA = 0.f;
    if (h0 > 0) {
        A4 = x4[base4 + (long long)(h0 - 1) * WV + v];
        if (vs) lA = __ldg(&x[baseS + (long long)(h0 - 1) * W + w0 - 1]);
    }
    float4 B4 = x4[base4 + (long long)h0 * WV + v];
    float lB = vs ? __ldg(&x[baseS + (long long)h0 * W + w0 - 1]) : 0.f;
    float4 C4 = x4[base4 + (long long)h1 * WV + v];
    float lC = vs ? __ldg(&x[baseS + (long long)h1 * W + w0 - 1]) : 0.f;
    float4 D4 = make_float4(0.f, 0.f, 0.f, 0.f);
    float lD = 0.f;
    if (h1 < H - 1) {
        D4 = x4[base4 + (long long)(h1 + 1) * WV + v];
        if (vs) lD = __ldg(&x[baseS + (long long)(h1 + 1) * W + w0 - 1]);
    }

    // shifted (w-1) and centered views per row
    const float As[4] = {lA, A4.x, A4.y, A4.z};
    const float Bs[4] = {lB, B4.x, B4.y, B4.z};
    const float Cs[4] = {lC, C4.x, C4.y, C4.z};
    const float Ds[4] = {lD, D4.x, D4.y, D4.z};
    const float Bc[4] = {B4.x, B4.y, B4.z, B4.w};
    const float Cc[4] = {C4.x, C4.y, C4.z, C4.w};

    const bool hupA = (h0 > 0);        // G1 valid at h0
    const bool hdnD = (h1 < H - 1);    // G3 valid at h1
    // G3 at h0 (uses row h1) and G1 at h1 (uses row h0) are always row-valid.

    float g1a[4], g2a[4], g3a[4];   // position h0
    float g1b[4], g2b[4], g3b[4];   // position h1
#pragma unroll
    for (int k = 0; k < 4; ++k) {
        const bool wok = vs || (k > 0);
        float e;
        e = As[k] - Bc[k]; g1a[k] = (hupA && wok) ? __expf(-e * e) + bi : bi;
        e = Bs[k] - Bc[k]; g2a[k] = wok           ? __expf(-e * e) + bi : bi;
        e = Cs[k] - Bc[k]; g3a[k] = wok           ? __expf(-e * e) + bi : bi;
        e = Bs[k] - Cc[k]; g1b[k] = wok           ? __expf(-e * e) + bi : bi;
        e = Cs[k] - Cc[k]; g2b[k] = wok           ? __expf(-e * e) + bi : bi;
        e = Ds[k] - Cc[k]; g3b[k] = (hdnD && wok) ? __expf(-e * e) + bi : bi;
    }

    float4* __restrict__ o4 = reinterpret_cast<float4*>(out);
    const long long n4 = n_elems >> 2;           // float4 count per gate
    const long long p0 = base4 + (long long)h0 * WV + v;
    const long long p1 = p0 + WV;
    o4[p0]           = make_float4(g1a[0], g1a[1], g1a[2], g1a[3]);
    o4[p1]           = make_float4(g1b[0], g1b[1], g1b[2], g1b[3]);
    o4[p0 + n4]      = make_float4(g2a[0], g2a[1], g2a[2], g2a[3]);
    o4[p1 + n4]      = make_float4(g2b[0], g2b[1], g2b[2], g2b[3]);
    o4[p0 + 2 * n4]  = make_float4(g3a[0], g3a[1], g3a[2], g3a[3]);
    o4[p1 + 2 * n4]  = make_float4(g3b[0], g3b[1], g3b[2], g3b[3]);
}

extern "C" void kernel_launch(void* const* d_in, const int* in_sizes, int n_in,
                              void* d_out, int out_size) {
    const float* x    = (const float*)d_in[0];
    const float* bias = (const float*)d_in[1];
    float* out = (float*)d_out;

    const long long n_elems = (long long)in_sizes[0];          // 4*32*512*512
    const long long total_threads = n_elems / 8;               // 2 positions per thread
    const int threads = 256;
    const int blocks = (int)((total_threads + threads - 1) / threads);

    embeded_gate_kernel<<<blocks, threads>>>(x, bias, out, n_elems);
}

// round 4
// speedup vs baseline: 1.0228x; 1.0228x over previous
#include <cuda_runtime.h>

// x: (4, 32, 512, 512) fp32 ; bias: (1, 32, 1, 1) fp32
// out: [G1 | G2 | G3], each (4, 32, 512, 512) fp32
//
// G1[h,w] = (h>=1 && w>=1) ? exp(-(x[h-1,w-1]-x[h,w])^2) + bias : bias
// G2[h,w] = (w>=1)          ? exp(-(x[h,  w-1]-x[h,w])^2) + bias : bias
// G3[h,w] = (h<H-1 && w>=1) ? exp(-(x[h+1,w-1]-x[h,w])^2) + bias : bias
//
// One float4 per thread. Fully branchless: row indices clamped so all 6
// loads (3x LDG.128 + 3x LDG.32) issue unconditionally and front-batched;
// invalid border contributions are masked by selects.

#define H   512
#define WV  128           // float4 per row
#define N4  8388608u      // float4 per gate tensor (4*32*512*512/4)

__global__ __launch_bounds__(256) void embeded_gate_kernel(
    const float* __restrict__ x,
    const float* __restrict__ bias,
    float* __restrict__ out)
{
    const unsigned idx = blockIdx.x * 256u + threadIdx.x;   // == float4 linear index
    const unsigned v = idx & (WV - 1);
    const unsigned h = (idx >> 7) & (H - 1);
    const unsigned c = (idx >> 16) & 31u;

    const float bi = __ldg(&bias[c]);

    const bool hup = (h > 0);
    const bool hdn = (h < H - 1);
    const bool vs  = (v > 0);

    // clamped neighbor-row float4 indices (always in-bounds)
    const unsigned iu = hup ? idx - WV : idx;
    const unsigned id = hdn ? idx + WV : idx;
    const unsigned dv = vs ? 1u : 0u;   // scalar left-neighbor offset

    const float4* __restrict__ x4 = reinterpret_cast<const float4*>(x);

    // ---- 6 unconditional, independent loads (front-batched) ----
    const float4 cur4 = x4[idx];
    const float4 u4   = x4[iu];
    const float4 d4   = x4[id];
    const float  lc   = __ldg(&x[(idx << 2) - dv]);
    const float  lu   = __ldg(&x[(iu  << 2) - dv]);
    const float  ld   = __ldg(&x[(id  << 2) - dv]);

    const float cur[4] = {cur4.x, cur4.y, cur4.z, cur4.w};
    const float lf[4]  = {lc, cur4.x, cur4.y, cur4.z};
    const float up[4]  = {lu, u4.x,   u4.y,   u4.z};
    const float dn[4]  = {ld, d4.x,   d4.y,   d4.z};

    float g1[4], g2[4], g3[4];
#pragma unroll
    for (int k = 0; k < 4; ++k) {
        const bool wok = vs || (k > 0);     // global w index > 0
        float e1 = up[k] - cur[k];
        float e2 = lf[k] - cur[k];
        float e3 = dn[k] - cur[k];
        float v1 = __expf(-e1 * e1) + bi;
        float v2 = __expf(-e2 * e2) + bi;
        float v3 = __expf(-e3 * e3) + bi;
        g1[k] = (hup && wok) ? v1 : bi;
        g2[k] = (wok)        ? v2 : bi;
        g3[k] = (hdn && wok) ? v3 : bi;
    }

    float4* __restrict__ o4 = reinterpret_cast<float4*>(out);
    o4[idx]            = make_float4(g1[0], g1[1], g1[2], g1[3]);
    o4[idx + N4]       = make_float4(g2[0], g2[1], g2[2], g2[3]);
    o4[idx + 2u * N4]  = make_float4(g3[0], g3[1], g3[2], g3[3]);
}

extern "C" void kernel_launch(void* const* d_in, const int* in_sizes, int n_in,
                              void* d_out, int out_size) {
    const float* x    = (const float*)d_in[0];
    const float* bias = (const float*)d_in[1];
    float* out = (float*)d_out;

    const long long total_vec = (long long)in_sizes[0] / 4;   // 8,388,608 threads
    const int threads = 256;
    const int blocks = (int)((total_vec + threads - 1) / threads);

    embeded_gate_kernel<<<blocks, threads>>>(x, bias, out);
}

// round 5
// speedup vs baseline: 1.0272x; 1.0043x over previous
#include <cuda_runtime.h>

// x: (4, 32, 512, 512) fp32 ; bias: (1, 32, 1, 1) fp32
// out: [G1 | G2 | G3], each (4, 32, 512, 512) fp32
//
// G1[h,w] = (h>=1 && w>=1) ? exp(-(x[h-1,w-1]-x[h,w])^2) + bias : bias
// G2[h,w] = (w>=1)          ? exp(-(x[h,  w-1]-x[h,w])^2) + bias : bias
// G3[h,w] = (h<H-1 && w>=1) ? exp(-(x[h+1,w-1]-x[h,w])^2) + bias : bias
//
// One float4 per thread, fully branchless (clamped row indices, selects).
// Outputs stored write-through (__stwt): never re-read, keep L2 for x.

#define H   512
#define WV  128           // float4 per row
#define N4  8388608u      // float4 per gate tensor (4*32*512*512/4)

__global__ __launch_bounds__(256) void embeded_gate_kernel(
    const float* __restrict__ x,
    const float* __restrict__ bias,
    float* __restrict__ out)
{
    const unsigned idx = blockIdx.x * 256u + threadIdx.x;   // == float4 linear index
    const unsigned v = idx & (WV - 1);
    const unsigned h = (idx >> 7) & (H - 1);
    const unsigned c = (idx >> 16) & 31u;

    const float bi = __ldg(&bias[c]);

    const bool hup = (h > 0);
    const bool hdn = (h < H - 1);
    const bool vs  = (v > 0);

    // clamped neighbor-row float4 indices (always in-bounds)
    const unsigned iu = hup ? idx - WV : idx;
    const unsigned id = hdn ? idx + WV : idx;
    const unsigned dv = vs ? 1u : 0u;   // scalar left-neighbor offset

    const float4* __restrict__ x4 = reinterpret_cast<const float4*>(x);

    // ---- 6 unconditional, independent loads (front-batched) ----
    const float4 cur4 = x4[idx];
    const float4 u4   = x4[iu];
    const float4 d4   = x4[id];
    const float  lc   = __ldg(&x[(idx << 2) - dv]);
    const float  lu   = __ldg(&x[(iu  << 2) - dv]);
    const float  ld   = __ldg(&x[(id  << 2) - dv]);

    const float cur[4] = {cur4.x, cur4.y, cur4.z, cur4.w};
    const float lf[4]  = {lc, cur4.x, cur4.y, cur4.z};
    const float up[4]  = {lu, u4.x,   u4.y,   u4.z};
    const float dn[4]  = {ld, d4.x,   d4.y,   d4.z};

    float g1[4], g2[4], g3[4];
#pragma unroll
    for (int k = 0; k < 4; ++k) {
        const bool wok = vs || (k > 0);     // global w index > 0
        float e1 = up[k] - cur[k];
        float e2 = lf[k] - cur[k];
        float e3 = dn[k] - cur[k];
        float v1 = __expf(-e1 * e1) + bi;
        float v2 = __expf(-e2 * e2) + bi;
        float v3 = __expf(-e3 * e3) + bi;
        g1[k] = (hup && wok) ? v1 : bi;
        g2[k] = (wok)        ? v2 : bi;
        g3[k] = (hdn && wok) ? v3 : bi;
    }

    float4* __restrict__ o4 = reinterpret_cast<float4*>(out);
    __stwt(&o4[idx],           make_float4(g1[0], g1[1], g1[2], g1[3]));
    __stwt(&o4[idx + N4],      make_float4(g2[0], g2[1], g2[2], g2[3]));
    __stwt(&o4[idx + 2u * N4], make_float4(g3[0], g3[1], g3[2], g3[3]));
}

extern "C" void kernel_launch(void* const* d_in, const int* in_sizes, int n_in,
                              void* d_out, int out_size) {
    const float* x    = (const float*)d_in[0];
    const float* bias = (const float*)d_in[1];
    float* out = (float*)d_out;

    const long long total_vec = (long long)in_sizes[0] / 4;   // 8,388,608 threads
    const int threads = 256;
    const int blocks = (int)((total_vec + threads - 1) / threads);

    embeded_gate_kernel<<<blocks, threads>>>(x, bias, out);
}